// round 11
// baseline (speedup 1.0000x reference)
#include <cuda_runtime.h>
#include <cuda_fp16.h>
#include <cstdint>

// Problem constants (fixed by setup_inputs)
#define BATCH   8
#define HH      128
#define WW      128
#define CC      256
#define HID     64
#define NTOK    (HH*WW)          // 16384 tokens per batch
#define NP      1024
#define KKEEP   768
#define TOK_ALL (BATCH*NTOK)     // 131072
#define BM      256
#define NBLK    (TOK_ALL/BM)     // 512
#define NSTEPS  16               // k16 steps
#define RING    5                // ring depth (stages)
#define THREADS 384              // 8 consumer + 4 producer warps

// Scratch (device globals — no allocation allowed)
__device__ float    g_imp[TOK_ALL];
__device__ unsigned g_key[BATCH*NP];
__device__ unsigned g_ball[BATCH*32];

// ---------------- SMEM layout (bytes) ----------------
// BH/BL: w1 hi/lo, 8x8-tile blocked fp16 (tile idx = k8*8+n8, 128B/tile): 32KB each.
// BL must sit at BH+32768 (fused hi/lo LDSM addressing via lane>>4).
// Ring: RING stages x 16KB; stage = A hi (8KB, 64 tiles of 128B) + A lo (+8192).
//   A tile layout: tile = (row>>3)*2 + (k>>3); byte = (row&7)*16 + (k&7)*2.
#define OFF_BH   0
#define OFF_BL   32768
#define OFF_B1   65536
#define OFF_W2   65792
#define OFF_MBF  66048            // full[RING] mbarriers (8B each)
#define OFF_MBE  (66048 + 8*RING) // empty[RING]
#define OFF_AST  66176            // 128B aligned
#define STAGE_B  16384
#define SMEM_SZ  (OFF_AST + RING*STAGE_B)   // 148096

// ---------------- asm helpers ----------------
static __device__ __forceinline__ uint32_t smem_u32(const void* p) {
    uint32_t a;
    asm("{ .reg .u64 t; cvta.to.shared.u64 t, %1; cvt.u32.u64 %0, t; }" : "=r"(a) : "l"(p));
    return a;
}
static __device__ __forceinline__ uint32_t h2u(__half2 h) {
    return *reinterpret_cast<uint32_t*>(&h);
}
#define LDSM_X4(r, a) \
    asm volatile("ldmatrix.sync.aligned.m8n8.x4.shared.b16 {%0,%1,%2,%3}, [%4];" \
        : "=r"((r)[0]), "=r"((r)[1]), "=r"((r)[2]), "=r"((r)[3]) : "r"(a))
#define LDSM_X4T(r, a) \
    asm volatile("ldmatrix.sync.aligned.m8n8.x4.trans.shared.b16 {%0,%1,%2,%3}, [%4];" \
        : "=r"((r)[0]), "=r"((r)[1]), "=r"((r)[2]), "=r"((r)[3]) : "r"(a))
#define MMA16816(d, a, b) \
    asm volatile("mma.sync.aligned.m16n8k16.row.col.f32.f16.f16.f32 " \
        "{%0,%1,%2,%3}, {%4,%5,%6,%7}, {%8,%9}, {%0,%1,%2,%3};" \
        : "+f"((d)[0]), "+f"((d)[1]), "+f"((d)[2]), "+f"((d)[3]) \
        : "r"((a)[0]), "r"((a)[1]), "r"((a)[2]), "r"((a)[3]), "r"((b)[0]), "r"((b)[1]))
#define STS128(a, r0, r1, r2, r3) \
    asm volatile("st.shared.v4.b32 [%0], {%1,%2,%3,%4};" \
                 :: "r"(a), "r"(r0), "r"(r1), "r"(r2), "r"(r3) : "memory")
#define MBARRIER_INIT(mb, n) \
    asm volatile("mbarrier.init.shared.b64 [%0], %1;" :: "r"((uint32_t)(mb)), "r"((uint32_t)(n)) : "memory")
#define MBARRIER_ARRIVE(mb) \
    asm volatile("mbarrier.arrive.shared.b64 _, [%0];" :: "r"((uint32_t)(mb)) : "memory")
#define MBARRIER_WAIT_PARITY(mb, par) do { \
    uint32_t _mb = (uint32_t)(mb); uint32_t _p = (uint32_t)(par); uint32_t _done; \
    asm volatile("{\n\t.reg .pred p;\n\t" \
        "mbarrier.try_wait.parity.shared.b64 p, [%1], %2;\n\t" \
        "selp.b32 %0, 1, 0, p;\n\t}" : "=r"(_done) : "r"(_mb), "r"(_p) : "memory"); \
    while (!_done) { \
        asm volatile("{\n\t.reg .pred p;\n\t" \
            "mbarrier.try_wait.parity.shared.b64 p, [%1], %2;\n\t" \
            "selp.b32 %0, 1, 0, p;\n\t}" : "=r"(_done) : "r"(_mb), "r"(_p) : "memory"); \
    } } while (0)

static __device__ __forceinline__ float gelu_exact(float v) {
    return 0.5f * v * (1.0f + erff(v * 0.7071067811865476f));
}

// split one float2 into hi/lo fp16x2 register pair
static __device__ __forceinline__ void split_f2(float2 v, uint32_t& hi, uint32_t& lo) {
    __half2 h = __floats2half2_rn(v.x, v.y);
    float2 hf = __half22float2(h);
    __half2 l = __floats2half2_rn(v.x - hf.x, v.y - hf.y);
    hi = h2u(h); lo = h2u(l);
}
// split float4 -> two hi half2 + two lo half2
static __device__ __forceinline__ void split_f4(float4 v, uint32_t& h0, uint32_t& h1,
                                                uint32_t& l0, uint32_t& l1) {
    split_f2(make_float2(v.x, v.y), h0, l0);
    split_f2(make_float2(v.z, v.w), h1, l1);
}

// ============ Kernel A: warp-specialized fp16-split HMMA MLP ============
// H = gelu(X[131072,256] @ W1[256,64] + b1); imp = sigmoid(H @ w2 + b2)
// 3-product fp16 split (err ~1e-7 << score order-stat gaps).
// Warps 8-11 produce A stages (LDG + split + STS); warps 0-7 consume
// (LDSM + MMA only). 5-stage mbarrier ring decouples DRAM from tensor.
__global__ __launch_bounds__(THREADS) void score_mma(
    const float* __restrict__ tokens,
    const float* __restrict__ w1,
    const float* __restrict__ b1,
    const float* __restrict__ w2,
    const float* __restrict__ b2)
{
    extern __shared__ char sm[];
    const uint32_t sb = smem_u32(sm);
    const int tid = threadIdx.x;
    const int lane = tid & 31, wid = tid >> 5;      // 12 warps
    const int g = lane >> 2, tig = lane & 3;

    if (tid < 64) {
        ((float*)(sm + OFF_B1))[tid] = b1[tid];
        ((float*)(sm + OFF_W2))[tid] = w2[tid];
    }
    if (tid == 0) {
#pragma unroll
        for (int st = 0; st < RING; ++st) {
            MBARRIER_INIT(sb + OFF_MBF + st * 8, 128);   // 4 producer warps arrive
            MBARRIER_INIT(sb + OFF_MBE + st * 8, 256);   // 8 consumer warps arrive
        }
    }
    const float b2v = b2[0];

    // stage w1 hi/lo once: tile idx (k>>3)*8 + (n>>3), byte (k&7)*16 + (n&7)*2
    for (int pi = tid; pi < 8192; pi += THREADS) {
        int k = pi >> 5, n = (pi & 31) * 2;
        float2 v = *(const float2*)(w1 + k * HID + n);
        uint32_t hb, lb;
        split_f2(v, hb, lb);
        uint32_t off = (uint32_t)(((k >> 3) * 8 + (n >> 3)) * 128 + (k & 7) * 16 + (n & 7) * 2);
        *(uint32_t*)(sm + OFF_BH + off) = hb;
        *(uint32_t*)(sm + OFF_BL + off) = lb;
    }
    __syncthreads();    // barriers + B visible; roles diverge after this

    if (wid < 8) {
        // ================= CONSUMER =================
        const uint32_t b_base = sb + OFF_BH + (uint32_t)(lane >> 4) * 32768u
                              + (uint32_t)((lane >> 3) & 1) * 1024u
                              + (uint32_t)(lane & 7) * 16u;
        // A LDSM per-lane offset within stage (row = wid*32+mi*16+(lane&15), kt = lane>>4)
        uint32_t aoff[2];
#pragma unroll
        for (int mi = 0; mi < 2; ++mi)
            aoff[mi] = (uint32_t)((((wid * 4 + mi * 2 + ((lane >> 3) & 1)) * 2 + (lane >> 4)) * 128)
                                  + (lane & 7) * 16);

        float acc[2][8][4];
#pragma unroll
        for (int mi = 0; mi < 2; ++mi)
#pragma unroll
            for (int nt = 0; nt < 8; ++nt)
#pragma unroll
                for (int q = 0; q < 4; ++q) acc[mi][nt][q] = 0.0f;

#pragma unroll
        for (int s = 0; s < NSTEPS; ++s) {
            const int slot = s % RING;
            const uint32_t stg = sb + OFF_AST + (uint32_t)slot * STAGE_B;
            MBARRIER_WAIT_PARITY(sb + OFF_MBF + slot * 8, (s / RING) & 1);

            uint32_t ah[2][4], al[2][4];
#pragma unroll
            for (int mi = 0; mi < 2; ++mi) {
                LDSM_X4(ah[mi], stg + aoff[mi]);
                LDSM_X4(al[mi], stg + 8192 + aoff[mi]);
            }
            MBARRIER_ARRIVE(sb + OFF_MBE + slot * 8);    // regs hold A; stage reusable

            uint32_t b4[8][4];
#pragma unroll
            for (int nt = 0; nt < 8; ++nt)
                LDSM_X4T(b4[nt], b_base + (uint32_t)((s * 16 + nt) * 128));

#pragma unroll
            for (int nt = 0; nt < 8; ++nt)
#pragma unroll
                for (int mi = 0; mi < 2; ++mi)
                    MMA16816(acc[mi][nt], ah[mi], b4[nt]);      // hi*hi
#pragma unroll
            for (int nt = 0; nt < 8; ++nt)
#pragma unroll
                for (int mi = 0; mi < 2; ++mi)
                    MMA16816(acc[mi][nt], ah[mi], b4[nt] + 2);  // hi*lo
#pragma unroll
            for (int nt = 0; nt < 8; ++nt)
#pragma unroll
                for (int mi = 0; mi < 2; ++mi)
                    MMA16816(acc[mi][nt], al[mi], b4[nt]);      // lo*hi
        }

        // ---- epilogue: gelu(h+b1)*w2, reduce 64 cols, sigmoid (R3-proven) ----
        const float* b1s = (const float*)(sm + OFF_B1);
        const float* w2s = (const float*)(sm + OFF_W2);
#pragma unroll
        for (int mi = 0; mi < 2; ++mi) {
            float p0 = 0.0f, p1 = 0.0f;
#pragma unroll
            for (int nt = 0; nt < 8; ++nt) {
                int c0 = nt * 8 + tig * 2, c1 = c0 + 1;
                float bb0 = b1s[c0], bb1 = b1s[c1];
                float ww0 = w2s[c0], ww1 = w2s[c1];
                p0 += gelu_exact(acc[mi][nt][0] + bb0) * ww0
                    + gelu_exact(acc[mi][nt][1] + bb1) * ww1;
                p1 += gelu_exact(acc[mi][nt][2] + bb0) * ww0
                    + gelu_exact(acc[mi][nt][3] + bb1) * ww1;
            }
            p0 += __shfl_xor_sync(0xffffffffu, p0, 1);
            p0 += __shfl_xor_sync(0xffffffffu, p0, 2);
            p1 += __shfl_xor_sync(0xffffffffu, p1, 1);
            p1 += __shfl_xor_sync(0xffffffffu, p1, 2);
            if (tig == 0) {
                int r0 = blockIdx.x * BM + wid * 32 + mi * 16 + g;
                g_imp[r0]     = 1.0f / (1.0f + expf(-(p0 + b2v)));
                g_imp[r0 + 8] = 1.0f / (1.0f + expf(-(p1 + b2v)));
            }
        }
    } else {
        // ================= PRODUCER =================
        const int pw = wid - 8;                     // 0..3, rows pw*64..+63
        const int r0 = pw * 64 + lane;              // this lane's rows: r0, r0+32
        const float* rp0 = tokens + (size_t)(blockIdx.x * BM + r0) * CC;
        const float* rp1 = rp0 + (size_t)32 * CC;
        // STS bases (tile = (row>>3)*2 + kt, byte (row&7)*16); +8192 for lo
        const uint32_t so0 = (uint32_t)(((r0 >> 3) * 2) * 128 + (r0 & 7) * 16);
        const uint32_t so1 = (uint32_t)((((r0 + 32) >> 3) * 2) * 128 + (r0 & 7) * 16);

        float4 buf[2][8];                           // [phase][rowhalf*4 + q]
#pragma unroll
        for (int q = 0; q < 4; ++q) {
            buf[0][q]     = *(const float4*)(rp0 + q * 4);
            buf[0][4 + q] = *(const float4*)(rp1 + q * 4);
        }

#pragma unroll
        for (int s = 0; s < NSTEPS; ++s) {
            // issue next stage's LDGs first (overlap with wait+split+STS)
            if (s + 1 < NSTEPS) {
#pragma unroll
                for (int q = 0; q < 4; ++q) {
                    buf[(s + 1) & 1][q]     = *(const float4*)(rp0 + (s + 1) * 16 + q * 4);
                    buf[(s + 1) & 1][4 + q] = *(const float4*)(rp1 + (s + 1) * 16 + q * 4);
                }
            }
            const int slot = s % RING;
            if (s >= RING)
                MBARRIER_WAIT_PARITY(sb + OFF_MBE + slot * 8, (s / RING + 1) & 1);

            const uint32_t stg = sb + OFF_AST + (uint32_t)slot * STAGE_B;
            float4* bp = buf[s & 1];
#pragma unroll
            for (int rh = 0; rh < 2; ++rh) {
                const uint32_t sbase = stg + (rh ? so1 : so0);
#pragma unroll
                for (int kt = 0; kt < 2; ++kt) {
                    uint32_t hA0, hA1, lA0, lA1, hB0, hB1, lB0, lB1;
                    split_f4(bp[rh * 4 + kt * 2],     hA0, hA1, lA0, lA1);
                    split_f4(bp[rh * 4 + kt * 2 + 1], hB0, hB1, lB0, lB1);
                    uint32_t a = sbase + (uint32_t)(kt * 128);
                    STS128(a,        hA0, hA1, hB0, hB1);
                    STS128(a + 8192, lA0, lA1, lB0, lB1);
                }
            }
            MBARRIER_ARRIVE(sb + OFF_MBF + slot * 8);
        }
    }
}

// ============ Kernel B1: patch scores -> ordered-uint keys (R7-proven) ============
__global__ __launch_bounds__(256) void pscore_kernel()
{
    const int pg = blockIdx.x * 256 + threadIdx.x;   // 8192 patches
    const int b = pg >> 10, p = pg & (NP - 1);
    const int pr = p >> 5, pc = p & 31;
    const float* base = g_imp + b * NTOK;
    float sum = 0.0f;
#pragma unroll
    for (int i = 0; i < 4; i++) {
        float4 v = *(const float4*)(base + (pr * 4 + i) * WW + pc * 4);
        sum += (v.x + v.y) + (v.z + v.w);
    }
    g_key[pg] = __float_as_uint(sum);   // sums of sigmoids > 0: uint order == float order
}

// ============ Kernel B2: stable top-768 rank -> keep ballots (R7-proven) ============
__global__ __launch_bounds__(128) void rank_kernel()
{
    __shared__ unsigned sk[NP];
    const int b = blockIdx.x >> 3;
    const int tid = threadIdx.x;
    const int p = (blockIdx.x & 7) * 128 + tid;

#pragma unroll
    for (int i = 0; i < 8; ++i)
        sk[tid + i * 128] = g_key[b * NP + tid + i * 128];
    __syncthreads();

    const unsigned kp = sk[p];
    int rank = 0;
    const uint4* s4 = (const uint4*)sk;
#pragma unroll 4
    for (int j4 = 0; j4 < NP / 4; ++j4) {
        uint4 v = s4[j4];
        int j = j4 * 4;
        rank += (int)((v.x > kp) || (v.x == kp && (j + 0) < p));
        rank += (int)((v.y > kp) || (v.y == kp && (j + 1) < p));
        rank += (int)((v.z > kp) || (v.z == kp && (j + 2) < p));
        rank += (int)((v.w > kp) || (v.w == kp && (j + 3) < p));
    }
    const unsigned mask = __ballot_sync(0xffffffffu, rank < KKEEP);
    if ((tid & 31) == 0)
        g_ball[b * 32 + (p >> 5)] = mask;
}

// ============ Kernel C: ballot-decode + gather + spatial reassembly (R7-proven) ============
__global__ __launch_bounds__(128) void gather_kernel(
    const float* __restrict__ tokens, float* __restrict__ out)
{
    const int k = blockIdx.x;            // kept slot 0..767
    const int b = blockIdx.y;
    __shared__ int s_p;

    if (threadIdx.x < 32) {
        const int w = threadIdx.x;
        unsigned bal = g_ball[b * 32 + w];
        int cnt = __popc(bal);
        int pre = cnt;
#pragma unroll
        for (int d = 1; d < 32; d <<= 1) {
            int t = __shfl_up_sync(0xffffffffu, pre, d);
            if (w >= d) pre += t;
        }
        pre -= cnt;                      // exclusive prefix of kept count
        if (k >= pre && k < pre + cnt) {
            int bit = __fns(bal, 0, (k - pre) + 1);
            s_p = w * 32 + bit;
        }
    }
    __syncthreads();
    const int p = s_p;
    const int pr = p >> 5, pc = p & 31;
    const int kr = k >> 5, kc = k & 31;

    const float4* src = (const float4*)(tokens + (size_t)b * NTOK * CC);
    float4*       dst = (float4*)(out + (size_t)b * (KKEEP * 16) * CC);
    const int t = threadIdx.x;

#pragma unroll
    for (int i = 0; i < 4; i++) {
        size_t so   = (size_t)((pr * 4 + i) * WW + pc * 4) * (CC / 4);
        size_t dofs = (size_t)((kr * 4 + i) * WW + kc * 4) * (CC / 4);
#pragma unroll
        for (int it = 0; it < 2; it++) {
            int e = it * 128 + t;
            dst[dofs + e] = src[so + e];
        }
    }
}

// ============================ launch ============================
extern "C" void kernel_launch(void* const* d_in, const int* in_sizes, int n_in,
                              void* d_out, int out_size)
{
    const float* tokens = (const float*)d_in[0];
    const float* w1 = (const float*)d_in[1];
    const float* b1 = (const float*)d_in[2];
    const float* w2 = (const float*)d_in[3];
    const float* b2 = (const float*)d_in[4];
    (void)in_sizes; (void)n_in; (void)out_size;

    cudaFuncSetAttribute(score_mma, cudaFuncAttributeMaxDynamicSharedMemorySize, SMEM_SZ);
    score_mma<<<NBLK, THREADS, SMEM_SZ>>>(tokens, w1, b1, w2, b2);
    pscore_kernel<<<BATCH * NP / 256, 256>>>();
    rank_kernel<<<64, 128>>>();
    gather_kernel<<<dim3(KKEEP, BATCH), 128>>>(tokens, (float*)d_out);
}